// round 15
// baseline (speedup 1.0000x reference)
#include <cuda_runtime.h>
#include <cuda_fp16.h>
#include <cstdint>
#include <math.h>

#define HW 4096
#define PW 72
#define PHW 5184          // 72*72 ; half2 rows 16B-aligned
#define HIDC 128
#define BB 4
#define OO 8
#define CC 256

// One chunk = 16 cin x 9 taps. A: 9kt*8mtile*32lane*16B = 36864 B.
// B: 8 ckpairs x (6 rows x 72 u32), ck stride 456 u32 (456%32==8, bank-safe).
#define A_STAGE 36864
#define B_CKSTR 456
#define B_STAGE 14592
#define STAGE (A_STAGE + B_STAGE)      // 51456
#define CONV_DSM (2*STAGE)             // 102912 -> 1 CTA/SM (512 thr, 16 warps)

// Readout tile kernels: 64 ck x 4 rows staged once. 64*296 u32 tile.
#define RO_CKSTR 296
#define RO_TILE_U32 18944
#define RO_DSM ((RO_TILE_U32 + 576)*4 + 1024)   // tile + ws + reduce buf

// ---------------------------------------------------------------------------
// Scratch (device globals; allocation forbidden). Zero-initialized at load;
// borders of padded buffers are NEVER written -> stay zero across replays.
// Padded activation buffers are half2, cin-pair interleaved: [ch/2][y][x].
// ---------------------------------------------------------------------------
__device__ uint32_t g_pst0[BB*OO*(HIDC/2)*PHW];  // states ping (half2)
__device__ uint32_t g_pst1[BB*OO*(HIDC/2)*PHW];  // states pong (half2)
__device__ uint32_t g_pS[BB*(HIDC/2)*PHW];       // sum-over-objects (half2)
__device__ uint32_t g_pfeats[BB*(CC/2)*PHW];     // feats (half2)
__device__ float    g_pbase[2*BB*HIDC*PHW];      // enc base partials (fp32 padded)
__device__ float    g_T[2*BB*HIDC*HW];           // gcn term partials (fp32)
__device__ float    g_rpart[2*BB*HW];            // readout base partials
__device__ uint32_t g_wencp[HIDC*CC*9/2];        // packed fp16 enc weights
__device__ uint32_t g_w2p[HIDC*HIDC*9/2];        // packed W2
__device__ uint32_t g_wdp[HIDC*HIDC*9/2];        // packed W1-W2
__device__ uint32_t g_wrof[2*9*64];              // packed ro feats weights
__device__ uint32_t g_wroh[9*64];                // packed ro hid weights

// ---------------------------------------------------------------------------
#define CP16(dst, src) \
    asm volatile("cp.async.cg.shared.global [%0], [%1], 16;" \
                 :: "r"(dst), "l"(src) : "memory")

__device__ __forceinline__ uint32_t packh2(float lo, float hi) {
    __half2 h = __floats2half2_rn(lo, hi);
    return *(uint32_t*)&h;
}
__device__ __forceinline__ void mma_f16(float* c, const uint32_t* a,
                                        uint32_t b0, uint32_t b1) {
    asm("mma.sync.aligned.m16n8k16.row.col.f32.f16.f16.f32 "
        "{%0,%1,%2,%3}, {%4,%5,%6,%7}, {%8,%9}, {%0,%1,%2,%3};"
        : "+f"(c[0]), "+f"(c[1]), "+f"(c[2]), "+f"(c[3])
        : "r"(a[0]), "r"(a[1]), "r"(a[2]), "r"(a[3]), "r"(b0), "r"(b1));
}

// ---------------------------------------------------------------------------
// fp16 implicit-GEMM 3x3 conv. M=128 oc, N=256 px (4 image rows), chunk =
// 16 cin x 9 taps. 512 threads (16 warps: 2M x 8N), 1 CTA/SM. 2-stage
// cp.async, ONE barrier per chunk: at iter i the barrier proves compute(i-1)
// done, so issue(i+1) may overwrite stage (i+1)&1 (computed at i-1);
// wait_group(0) proves chunk i landed (issued a full chunk-compute ago).
// A per chunk is shared by 256 px -> half the A traffic of the 128-px tile.
// K-split via blockIdx.z (bias only on z==0).
// outMode: 0 = fp32 unpadded, 1 = half2 padded (oc-pair via shfl), 2 = fp32 padded.
// ---------------------------------------------------------------------------
template<int CIN>
__global__ void __launch_bounds__(512, 1)
conv_mma(const uint32_t* __restrict__ pin, long imgCkStride,
         const uint32_t* __restrict__ wpack,
         const float* __restrict__ bias,
         const float* __restrict__ addend, const float* __restrict__ addend2,
         int addDiv,
         void* __restrict__ outp, long outZStride, int outMode, int doRelu)
{
    extern __shared__ __align__(16) char dsm[];
    const int tid  = threadIdx.x;
    const int lane = tid & 31, wid = tid >> 5;
    const int wm   = wid & 1,  wn  = wid >> 1;   // 2 M x 8 N warps
    const int img  = blockIdx.y, row0 = blockIdx.x * 4, z = blockIdx.z;
    constexpr int nchunk = CIN / 16;
    const uint32_t* pimg = pin + (long)img * imgCkStride + (long)z * (CIN/2) * PHW;
    const uint32_t* wp   = wpack + (long)z * (CIN/16) * 9216;
    const uint32_t smbase = (uint32_t)__cvta_generic_to_shared(dsm);

    float acc[4][4][4];
    #pragma unroll
    for (int mt = 0; mt < 4; mt++)
        #pragma unroll
        for (int nt = 0; nt < 4; nt++)
            #pragma unroll
            for (int e = 0; e < 4; e++) acc[mt][nt][e] = 0.f;

    auto issueChunk = [&](int ci) {
        const uint32_t abase = smbase + (ci & 1) * STAGE;
        const uint32_t bbase = abase + A_STAGE;
        const uint32_t* asrc = wp + (long)ci * 9216;
        #pragma unroll
        for (int j = 0; j < 5; j++) {                 // 2304 16B lines
            const int u = tid + j * 512;
            if (u < 2304) CP16(abase + u * 16, asrc + u * 4);
        }
        #pragma unroll
        for (int v = 0; v < 2; v++) {                 // 864 16B lines
            const int o = tid + v * 512;
            if (o < 864) {
                const int ck = o / 108, rem = o % 108;
                const int rI = rem / 18, q = rem % 18;
                const uint32_t* src = pimg + (long)(ci * 8 + ck) * PHW
                                      + (row0 + rI) * PW + q * 4;
                CP16(bbase + (ck * B_CKSTR + rI * 72 + q * 4) * 4, src);
            }
        }
        asm volatile("cp.async.commit_group;" ::: "memory");
    };

    auto compute = [&](int s) {
        const uint4*    As = (const uint4*)(dsm + s * STAGE);
        const uint32_t* Bs = (const uint32_t*)(dsm + s * STAGE + A_STAGE);
        #pragma unroll
        for (int kt = 0; kt < 9; kt++) {
            const int dy = kt / 3 - 1, dx = kt % 3 - 1;
            uint4 a[4];
            #pragma unroll
            for (int mt = 0; mt < 4; mt++)
                a[mt] = As[(kt * 8 + wm * 4 + mt) * 32 + lane];
            #pragma unroll
            for (int nt = 0; nt < 4; nt++) {
                const int n    = wn * 32 + nt * 8 + (lane >> 2);
                const int rowi = (n >> 6) + dy + 1;   // 0..5
                const int x    = (n & 63) + 1 + dx;
                const int c    = lane & 3;
                const uint32_t b0 = Bs[c * B_CKSTR + rowi * 72 + x];
                const uint32_t b1 = Bs[(c + 4) * B_CKSTR + rowi * 72 + x];
                #pragma unroll
                for (int mt = 0; mt < 4; mt++)
                    mma_f16(acc[mt][nt], (const uint32_t*)&a[mt], b0, b1);
            }
        }
    };

    issueChunk(0);
    for (int i = 0; i < nchunk; i++) {
        asm volatile("cp.async.wait_group 0;" ::: "memory");
        __syncthreads();
        if (i + 1 < nchunk) issueChunk(i + 1);
        compute(i & 1);
    }

    // ---- epilogue
    const int addImg = addDiv ? (img / addDiv) : 0;
    #pragma unroll
    for (int mt = 0; mt < 4; mt++) {
        #pragma unroll
        for (int h = 0; h < 2; h++) {
            const int oc = wm * 64 + mt * 16 + (lane >> 2) + h * 8;
            const float bv = (bias && z == 0) ? bias[oc] : 0.f;
            #pragma unroll
            for (int nt = 0; nt < 4; nt++) {
                const int n = wn * 32 + nt * 8 + 2 * (lane & 3);
                const int r = n >> 6, x = n & 63;      // r in 0..3
                float v0 = acc[mt][nt][2 * h + 0] + bv;
                float v1 = acc[mt][nt][2 * h + 1] + bv;
                const long aoff = ((long)addImg * HIDC + oc) * HW
                                  + (row0 + r) * 64 + x;
                if (addend) {
                    const float2 ad = *(const float2*)(addend + aoff);
                    v0 += ad.x; v1 += ad.y;
                }
                if (addend2) {
                    const float2 ad = *(const float2*)(addend2 + aoff);
                    v0 += ad.x; v1 += ad.y;
                }
                if (doRelu) { v0 = fmaxf(v0, 0.f); v1 = fmaxf(v1, 0.f); }
                if (outMode == 0) {
                    *(float2*)((float*)outp + z * outZStride
                               + ((long)img * HIDC + oc) * HW
                               + (row0 + r) * 64 + x) = make_float2(v0, v1);
                } else if (outMode == 2) {
                    float* op = (float*)outp + z * outZStride
                                + ((long)img * HIDC + oc) * PHW
                                + (row0 + r + 1) * PW + 1 + x;
                    op[0] = v0; op[1] = v1;
                } else {
                    const uint32_t own  = packh2(v0, v1);      // my oc, px x/x+1
                    const uint32_t part = __shfl_xor_sync(0xffffffffu, own, 4);
                    if (((lane >> 2) & 1) == 0) {              // even oc writes pair
                        uint32_t* op = (uint32_t*)outp
                            + ((long)img * (HIDC/2) + (oc >> 1)) * PHW
                            + (row0 + r + 1) * PW + 1 + x;
                        op[0] = (own & 0xFFFFu) | (part << 16);
                        op[1] = (own >> 16) | (part & 0xFFFF0000u);
                    }
                }
            }
        }
    }
}

// ---------------------------------------------------------------------------
// Fused prep: feats pad+pack | enc pack | gcn pack | ro pack, ONE launch.
// Fragment layout per 16-cin chunk (9216 u32): [kt(9)][mtile(8)][lane(32)][e(4)];
// oc = mtile*16 + (lane>>2) + ((e&1)<<3); cinpair = (lane&3) + ((e>>1)<<2).
// ---------------------------------------------------------------------------
#define NPAD ((long)BB*(CC/2)*PHW)   // 2654208
#define NE (HIDC*CC*9/2)             // 147456
#define NG (HIDC*HIDC*9/2)           // 73728
__global__ void prep_pad_all(const float* __restrict__ f,
                             const float* __restrict__ ew,
                             const float* __restrict__ gw,
                             const float* __restrict__ ro_w,
                             uint32_t* __restrict__ pf,
                             uint32_t* __restrict__ wencp,
                             uint32_t* __restrict__ w2p, uint32_t* __restrict__ wdp,
                             uint32_t* __restrict__ wrof, uint32_t* __restrict__ wroh)
{
    long gi = (long)blockIdx.x * 256 + threadIdx.x;
    if (gi < NPAD) {
        long ch = gi / PHW; int p = (int)(gi % PHW); int y = p / PW, x = p % PW;
        uint32_t v = 0;
        if (y >= 1 && y <= 64 && x >= 1 && x <= 64) {
            int b = (int)(ch >> 7), ck = (int)(ch & 127);
            const float* src = f + ((long)b * CC + 2 * ck) * HW + (y - 1) * 64 + (x - 1);
            v = packh2(src[0], src[HW]);
        }
        pf[gi] = v;
        return;
    }
    int idx = (int)(gi - NPAD);
    if (idx < NE) {
        int chunk = idx / 9216, rem = idx % 9216;
        int kt = rem / 1024, rem2 = rem % 1024;
        int mtile = rem2 / 128, r3 = rem2 % 128;
        int lane = r3 / 4, e = r3 % 4;
        int oc = mtile * 16 + (lane >> 2) + ((e & 1) << 3);
        int cin0 = chunk * 16 + ((lane & 3) + ((e >> 1) << 2)) * 2;
        wencp[idx] = packh2(ew[((long)oc * 257 + cin0) * 9 + kt],
                            ew[((long)oc * 257 + cin0 + 1) * 9 + kt]);
    } else if (idx < NE + NG) {
        int i2 = idx - NE;
        int chunk = i2 / 9216, rem = i2 % 9216;
        int kt = rem / 1024, rem2 = rem % 1024;
        int mtile = rem2 / 128, r3 = rem2 % 128;
        int lane = r3 / 4, e = r3 % 4;
        int oc = mtile * 16 + (lane >> 2) + ((e & 1) << 3);
        int cin0 = chunk * 16 + ((lane & 3) + ((e >> 1) << 2)) * 2;
        float a0 = gw[((long)oc * 2 * HIDC + cin0) * 9 + kt];
        float b0 = gw[((long)oc * 2 * HIDC + HIDC + cin0) * 9 + kt];
        float a1 = gw[((long)oc * 2 * HIDC + cin0 + 1) * 9 + kt];
        float b1 = gw[((long)oc * 2 * HIDC + HIDC + cin0 + 1) * 9 + kt];
        w2p[i2] = packh2(b0, b1);
        wdp[i2] = packh2(a0 - b0, a1 - b1);
    } else if (idx < NE + NG + 1152) {
        int r0 = idx - NE - NG;
        int zz = r0 / 576, r = r0 % 576, tap = r / 64, ck = r % 64;
        int ch0 = zz * 128 + 2 * ck;
        wrof[r0] = packh2(ro_w[ch0 * 9 + tap], ro_w[(ch0 + 1) * 9 + tap]);
    } else if (idx < NE + NG + 1728) {
        int r = idx - NE - NG - 1152, tap = r / 64, ck = r % 64;
        int ch0 = CC + 2 * ck;
        wroh[r] = packh2(ro_w[ch0 * 9 + tap], ro_w[(ch0 + 1) * 9 + tap]);
    }
}

// ---------------------------------------------------------------------------
// Fused enc-per-object + sum-over-objects. grid (16 pxblk, BB, 4 chgrp).
// Loops 8 objects in registers: base read once, states + S written.
// ---------------------------------------------------------------------------
__global__ void __launch_bounds__(256) enc_obj_sum(
    const float* __restrict__ masks, const float* __restrict__ enc_w,
    const float* __restrict__ pbase, uint32_t* __restrict__ pst,
    uint32_t* __restrict__ pS)
{
    __shared__ float wm2[32 * 9];
    const int tid = threadIdx.x;
    const int b = blockIdx.y, cg = blockIdx.z;
    const int p = blockIdx.x * 256 + tid;
    for (int t = tid; t < 288; t += 256) {
        int lch = t / 9, k = t - lch * 9;
        wm2[t] = enc_w[((long)(cg * 32 + lch) * 257 + 256) * 9 + k];
    }
    __syncthreads();
    const int y = p >> 6, x = p & 63;
    const int pp = (y + 1) * PW + x + 1;
    float m[8][9];
    #pragma unroll
    for (int o = 0; o < 8; o++) {
        const float* mk = masks + (long)(b * 8 + o) * HW;
        #pragma unroll
        for (int k = 0; k < 9; k++) {
            int gy = y - 1 + k / 3, gx = x - 1 + k % 3;
            m[o][k] = ((unsigned)gy < 64u && (unsigned)gx < 64u)
                        ? mk[gy * 64 + gx] : 0.f;
        }
    }
    const float* b1p = pbase + (long)b * HIDC * PHW;
    const float* b2p = b1p + (long)BB * HIDC * PHW;
    #pragma unroll 2
    for (int j = 0; j < 16; j++) {
        const int ck = cg * 16 + j;
        const int ch0 = 2 * ck;
        float base0 = b1p[(long)ch0 * PHW + pp] + b2p[(long)ch0 * PHW + pp];
        float base1 = b1p[(long)(ch0+1) * PHW + pp] + b2p[(long)(ch0+1) * PHW + pp];
        float sLo = 0.f, sHi = 0.f;
        #pragma unroll
        for (int o = 0; o < 8; o++) {
            float a0 = base0, a1 = base1;
            #pragma unroll
            for (int k = 0; k < 9; k++) {
                a0 = fmaf(wm2[(2*j) * 9 + k],   m[o][k], a0);
                a1 = fmaf(wm2[(2*j+1) * 9 + k], m[o][k], a1);
            }
            uint32_t h = packh2(fmaxf(a0, 0.f), fmaxf(a1, 0.f));
            pst[((long)(b * 8 + o) * (HIDC/2) + ck) * PHW + pp] = h;
            __half2 hh = *(__half2*)&h;
            sLo += __low2float(hh); sHi += __high2float(hh);
        }
        pS[((long)b * (HIDC/2) + ck) * PHW + pp] = packh2(sLo, sHi);
    }
}
// Vectorized sum-over-objects (uint4) for step 2.
__global__ void sumO4_k(const uint4* __restrict__ st, uint4* __restrict__ S) {
    long idx = (long)blockIdx.x * 256 + threadIdx.x;
    const long N = (long)BB * (HIDC/2) * (PHW/4);
    if (idx >= N) return;
    int b = (int)(idx / ((HIDC/2) * (PHW/4)));
    long r = idx - (long)b * (HIDC/2) * (PHW/4);
    const uint4* pp = st + (long)b * OO * (HIDC/2) * (PHW/4) + r;
    float lo[4] = {0,0,0,0}, hi[4] = {0,0,0,0};
    #pragma unroll
    for (int o = 0; o < OO; o++) {
        uint4 v = pp[(long)o * (HIDC/2) * (PHW/4)];
        const uint32_t* w = (const uint32_t*)&v;
        #pragma unroll
        for (int c = 0; c < 4; c++) {
            __half2 h = *(__half2*)&w[c];
            lo[c] += __low2float(h); hi[c] += __high2float(h);
        }
    }
    uint4 out;
    uint32_t* ow = (uint32_t*)&out;
    #pragma unroll
    for (int c = 0; c < 4; c++) ow[c] = packh2(lo[c], hi[c]);
    S[idx] = out;
}

// ---------------------------------------------------------------------------
// Readout tile kernels: stage 64 ck x 4 padded rows via ONE cp.async round,
// one barrier, then fp32-accum dot over (ck, tap). 2 threads per px split ck.
// ---------------------------------------------------------------------------
__global__ void __launch_bounds__(256) ro_base_k(
    const uint32_t* __restrict__ pfeats, const uint32_t* __restrict__ wrof,
    const float* __restrict__ ro_b, float* __restrict__ rpart)
{
    extern __shared__ __align__(16) uint32_t sm[];
    uint32_t* ws  = sm + RO_TILE_U32;
    float*    red = (float*)(ws + 576);
    const int tid = threadIdx.x;
    const int img = blockIdx.y, z = blockIdx.z, row0 = blockIdx.x * 2;
    const uint32_t* pimg = pfeats + (long)img * (CC/2) * PHW + (long)z * 64 * PHW;
    const uint32_t smb = (uint32_t)__cvta_generic_to_shared(sm);
    #pragma unroll
    for (int j = 0; j < 18; j++) {
        const int o = tid + j * 256;          // 4608 lines
        const int ck = o / 72, rem = o % 72, rI = rem / 18, q = rem % 18;
        CP16(smb + (ck * RO_CKSTR + rI * 72 + q * 4) * 4,
             pimg + (long)ck * PHW + (row0 + rI) * PW + q * 4);
    }
    for (int t = tid; t < 576; t += 256) ws[t] = wrof[z * 576 + t];
    asm volatile("cp.async.commit_group;" ::: "memory");
    asm volatile("cp.async.wait_group 0;" ::: "memory");
    __syncthreads();

    const int px = tid & 127, ckh = tid >> 7;
    const int r = px >> 6, x = px & 63;
    float acc = 0.f;
    for (int ck = ckh * 32; ck < ckh * 32 + 32; ck++) {
        #pragma unroll
        for (int tap = 0; tap < 9; tap++) {
            const int dy = tap / 3 - 1, dx = tap % 3 - 1;
            uint32_t bv = sm[ck * RO_CKSTR + (r + 1 + dy) * 72 + (x + 1 + dx)];
            float2 bf = __half22float2(*(__half2*)&bv);
            float2 wf = __half22float2(*(__half2*)&ws[tap * 64 + ck]);
            acc = fmaf(bf.x, wf.x, acc);
            acc = fmaf(bf.y, wf.y, acc);
        }
    }
    red[tid] = acc;
    __syncthreads();
    if (tid < 128) {
        float s = red[tid] + red[tid + 128] + (z == 0 ? ro_b[0] : 0.f);
        rpart[((long)z * BB + img) * HW + (row0 + r) * 64 + x] = s;
    }
}
__global__ void __launch_bounds__(256) ro_obj_k(
    const uint32_t* __restrict__ pst, const uint32_t* __restrict__ wroh,
    const float* __restrict__ rpart, float* __restrict__ outp)
{
    extern __shared__ __align__(16) uint32_t sm[];
    uint32_t* ws  = sm + RO_TILE_U32;
    float*    red = (float*)(ws + 576);
    const int tid = threadIdx.x;
    const int img = blockIdx.y, row0 = blockIdx.x * 2;
    const uint32_t* pimg = pst + (long)img * (HIDC/2) * PHW;
    const uint32_t smb = (uint32_t)__cvta_generic_to_shared(sm);
    #pragma unroll
    for (int j = 0; j < 18; j++) {
        const int o = tid + j * 256;
        const int ck = o / 72, rem = o % 72, rI = rem / 18, q = rem % 18;
        CP16(smb + (ck * RO_CKSTR + rI * 72 + q * 4) * 4,
             pimg + (long)ck * PHW + (row0 + rI) * PW + q * 4);
    }
    for (int t = tid; t < 576; t += 256) ws[t] = wroh[t];
    asm volatile("cp.async.commit_group;" ::: "memory");
    asm volatile("cp.async.wait_group 0;" ::: "memory");
    __syncthreads();

    const int px = tid & 127, ckh = tid >> 7;
    const int r = px >> 6, x = px & 63;
    float acc = 0.f;
    for (int ck = ckh * 32; ck < ckh * 32 + 32; ck++) {
        #pragma unroll
        for (int tap = 0; tap < 9; tap++) {
            const int dy = tap / 3 - 1, dx = tap % 3 - 1;
            uint32_t bv = sm[ck * RO_CKSTR + (r + 1 + dy) * 72 + (x + 1 + dx)];
            float2 bf = __half22float2(*(__half2*)&bv);
            float2 wf = __half22float2(*(__half2*)&ws[tap * 64 + ck]);
            acc = fmaf(bf.x, wf.x, acc);
            acc = fmaf(bf.y, wf.y, acc);
        }
    }
    red[tid] = acc;
    __syncthreads();
    if (tid < 128) {
        const int b = img >> 3;
        const long po = (long)b * HW + (row0 + r) * 64 + x;
        float zl = red[tid] + red[tid + 128]
                 + rpart[po] + rpart[(long)BB * HW + po];
        outp[(long)img * HW + (row0 + r) * 64 + x] = 1.f / (1.f + expf(-zl));
    }
}

// ---------------------------------------------------------------------------
extern "C" void kernel_launch(void* const* d_in, const int* in_sizes, int n_in,
                              void* d_out, int out_size)
{
    const float* feats = (const float*)d_in[0];
    const float* masks = (const float*)d_in[1];
    const float* enc_w = (const float*)d_in[4];
    const float* enc_b = (const float*)d_in[5];
    const float* gcn_w = (const float*)d_in[6];
    const float* gcn_b = (const float*)d_in[7];
    const float* ro_w  = (const float*)d_in[8];
    const float* ro_b  = (const float*)d_in[9];
    float* outp = (float*)d_out;

    uint32_t *pst0, *pst1, *pS, *pfeats, *wencp, *w2p, *wdp, *wrof, *wroh;
    float *pbase, *T, *rpart;
    cudaGetSymbolAddress((void**)&pst0,   g_pst0);
    cudaGetSymbolAddress((void**)&pst1,   g_pst1);
    cudaGetSymbolAddress((void**)&pS,     g_pS);
    cudaGetSymbolAddress((void**)&pfeats, g_pfeats);
    cudaGetSymbolAddress((void**)&pbase,  g_pbase);
    cudaGetSymbolAddress((void**)&T,      g_T);
    cudaGetSymbolAddress((void**)&rpart,  g_rpart);
    cudaGetSymbolAddress((void**)&wencp,  g_wencp);
    cudaGetSymbolAddress((void**)&w2p,    g_w2p);
    cudaGetSymbolAddress((void**)&wdp,    g_wdp);
    cudaGetSymbolAddress((void**)&wrof,   g_wrof);
    cudaGetSymbolAddress((void**)&wroh,   g_wroh);

    cudaFuncSetAttribute(conv_mma<64>,
                         cudaFuncAttributeMaxDynamicSharedMemorySize, CONV_DSM);
    cudaFuncSetAttribute(conv_mma<128>,
                         cudaFuncAttributeMaxDynamicSharedMemorySize, CONV_DSM);
    cudaFuncSetAttribute(ro_base_k,
                         cudaFuncAttributeMaxDynamicSharedMemorySize, RO_DSM);
    cudaFuncSetAttribute(ro_obj_k,
                         cudaFuncAttributeMaxDynamicSharedMemorySize, RO_DSM);

    // fused pad + weight prep
    {
        long total = NPAD + NE + NG + 1728;
        prep_pad_all<<<(int)((total + 255) / 256), 256>>>(
            feats, enc_w, gcn_w, ro_w, pfeats, wencp, w2p, wdp, wrof, wroh);
    }

    // enc base, K-split z=2: partials -> pbase[0], pbase[zstride]
    conv_mma<128><<<dim3(16, BB, 2), 512, CONV_DSM>>>(
        pfeats, (long)(CC/2)*PHW, wencp, enc_b, nullptr, nullptr, 0,
        pbase, (long)BB*HIDC*PHW, 2, 0);
    // fused enc per-object + sumO -> pst0, pS
    enc_obj_sum<<<dim3(16, BB, 4), 256>>>(masks, enc_w, pbase, pst0, pS);

    // step 1
    conv_mma<64><<<dim3(16, BB, 2), 512, CONV_DSM>>>(
        pS, (long)(HIDC/2)*PHW, w2p, gcn_b, nullptr, nullptr, 0,
        T, (long)BB*HIDC*HW, 0, 0);
    conv_mma<128><<<dim3(16, BB*OO, 1), 512, CONV_DSM>>>(
        pst0, (long)(HIDC/2)*PHW, wdp, nullptr,
        T, T + (long)BB*HIDC*HW, OO, pst1, 0, 1, 1);
    sumO4_k<<<(int)(((long)BB*(HIDC/2)*(PHW/4) + 255)/256), 256>>>(
        (const uint4*)pst1, (uint4*)pS);

    // step 2
    conv_mma<64><<<dim3(16, BB, 2), 512, CONV_DSM>>>(
        pS, (long)(HIDC/2)*PHW, w2p, gcn_b, nullptr, nullptr, 0,
        T, (long)BB*HIDC*HW, 0, 0);
    conv_mma<128><<<dim3(16, BB*OO, 1), 512, CONV_DSM>>>(
        pst1, (long)(HIDC/2)*PHW, wdp, nullptr,
        T, T + (long)BB*HIDC*HW, OO, pst0, 0, 1, 1);

    ro_base_k<<<dim3(32, BB, 2), 256, RO_DSM>>>(pfeats, wrof, ro_b, rpart);
    ro_obj_k<<<dim3(32, BB*OO), 256, RO_DSM>>>(pst0, wroh, rpart, outp);
}

// round 16
// speedup vs baseline: 1.1762x; 1.1762x over previous
#include <cuda_runtime.h>
#include <cuda_fp16.h>
#include <cstdint>
#include <math.h>

#define HW 4096
#define PW 72
#define PHW 5184          // 72*72 ; half2 rows 16B-aligned
#define HIDC 128
#define BB 4
#define OO 8
#define CC 256

// One chunk = 16 cin x 9 taps. A: 9kt*8mtile*32lane*16B = 36864 B.
// B: 8 ckpairs x (4 rows x 72 u32), ck stride 296 u32 (bank-spread) = 9472 B.
#define A_STAGE 36864
#define B_CKSTR 296
#define B_STAGE 9472
#define STAGE (A_STAGE + B_STAGE)      // 46336
#define CONV_DSM (2*STAGE)             // 92672 -> 2 CTA/SM

// Readout tile kernels: 64 ck x 4 rows staged once. 64*296 u32 tile.
#define RO_TILE_U32 18944
#define RO_DSM ((RO_TILE_U32 + 576)*4 + 1024)   // tile + ws + reduce buf

// ---------------------------------------------------------------------------
// Scratch (device globals; allocation forbidden). Zero-initialized at load;
// borders of padded buffers are NEVER written -> stay zero across replays.
// Padded activation buffers are half2, cin-pair interleaved: [ch/2][y][x].
// ---------------------------------------------------------------------------
__device__ uint32_t g_pst0[BB*OO*(HIDC/2)*PHW];  // states ping (half2)
__device__ uint32_t g_pst1[BB*OO*(HIDC/2)*PHW];  // states pong (half2)
__device__ uint32_t g_pS[BB*(HIDC/2)*PHW];       // sum-over-objects (half2)
__device__ uint32_t g_pfeats[BB*(CC/2)*PHW];     // feats (half2)
__device__ float    g_pbase[2*BB*HIDC*PHW];      // enc base partials (fp32 padded)
__device__ float    g_T[2*BB*HIDC*HW];           // gcn term partials (fp32)
__device__ float    g_rpart[2*BB*HW];            // readout base partials
__device__ uint32_t g_wencp[HIDC*CC*9/2];        // packed fp16 enc weights
__device__ uint32_t g_w2p[HIDC*HIDC*9/2];        // packed W2
__device__ uint32_t g_wdp[HIDC*HIDC*9/2];        // packed W1-W2
__device__ uint32_t g_wrof[2*9*64];              // packed ro feats weights
__device__ uint32_t g_wroh[9*64];                // packed ro hid weights

// ---------------------------------------------------------------------------
#define CP16(dst, src) \
    asm volatile("cp.async.cg.shared.global [%0], [%1], 16;" \
                 :: "r"(dst), "l"(src) : "memory")

__device__ __forceinline__ uint32_t packh2(float lo, float hi) {
    __half2 h = __floats2half2_rn(lo, hi);
    return *(uint32_t*)&h;
}
__device__ __forceinline__ void mma_f16(float* c, const uint32_t* a,
                                        uint32_t b0, uint32_t b1) {
    asm("mma.sync.aligned.m16n8k16.row.col.f32.f16.f16.f32 "
        "{%0,%1,%2,%3}, {%4,%5,%6,%7}, {%8,%9}, {%0,%1,%2,%3};"
        : "+f"(c[0]), "+f"(c[1]), "+f"(c[2]), "+f"(c[3])
        : "r"(a[0]), "r"(a[1]), "r"(a[2]), "r"(a[3]), "r"(b0), "r"(b1));
}

// ---------------------------------------------------------------------------
// fp16 implicit-GEMM 3x3 conv (R12-proven core, UNCHANGED). M=128 oc,
// N=128 px (2 rows), chunk = 16 cin x 9 taps. 2-stage cp.async, ONE barrier
// per chunk: at iter i the barrier proves compute(i-1) done, so issue(i+1)
// may overwrite stage (i+1)&1 (computed at i-1); wait_group(0) proves chunk
// i landed. K-split via blockIdx.z (bias only on z==0).
// outMode: 0 = fp32 unpadded, 1 = half2 padded (oc-pair via shfl), 2 = fp32 padded.
// ---------------------------------------------------------------------------
template<int CIN>
__global__ void __launch_bounds__(256, 2)
conv_mma(const uint32_t* __restrict__ pin, long imgCkStride,
         const uint32_t* __restrict__ wpack,
         const float* __restrict__ bias,
         const float* __restrict__ addend, int addDiv,
         void* __restrict__ outp, long outZStride, int outMode, int doRelu)
{
    extern __shared__ __align__(16) char dsm[];
    const int tid  = threadIdx.x;
    const int lane = tid & 31, wid = tid >> 5;
    const int wm   = wid & 1,  wn  = wid >> 1;
    const int img  = blockIdx.y, row0 = blockIdx.x * 2, z = blockIdx.z;
    constexpr int nchunk = CIN / 16;
    const uint32_t* pimg = pin + (long)img * imgCkStride + (long)z * (CIN/2) * PHW;
    const uint32_t* wp   = wpack + (long)z * (CIN/16) * 9216;
    const uint32_t smbase = (uint32_t)__cvta_generic_to_shared(dsm);

    float acc[4][4][4];
    #pragma unroll
    for (int mt = 0; mt < 4; mt++)
        #pragma unroll
        for (int nt = 0; nt < 4; nt++)
            #pragma unroll
            for (int e = 0; e < 4; e++) acc[mt][nt][e] = 0.f;

    auto issueChunk = [&](int ci) {
        const uint32_t abase = smbase + (ci & 1) * STAGE;
        const uint32_t bbase = abase + A_STAGE;
        const uint32_t* asrc = wp + (long)ci * 9216;
        #pragma unroll
        for (int j = 0; j < 9; j++) {                 // 2304 16B lines
            const int u = tid + j * 256;
            CP16(abase + u * 16, asrc + u * 4);
        }
        #pragma unroll
        for (int v = 0; v < 3; v++) {                 // 576 16B lines
            const int o = tid + v * 256;
            if (o < 576) {
                const int ck = o / 72, rem = o % 72;
                const int rI = rem / 18, q = rem % 18;
                const uint32_t* src = pimg + (long)(ci * 8 + ck) * PHW
                                      + (row0 + rI) * PW + q * 4;
                CP16(bbase + (ck * B_CKSTR + rI * 72 + q * 4) * 4, src);
            }
        }
        asm volatile("cp.async.commit_group;" ::: "memory");
    };

    auto compute = [&](int s) {
        const uint4*    As = (const uint4*)(dsm + s * STAGE);
        const uint32_t* Bs = (const uint32_t*)(dsm + s * STAGE + A_STAGE);
        #pragma unroll
        for (int kt = 0; kt < 9; kt++) {
            const int dy = kt / 3 - 1, dx = kt % 3 - 1;
            uint4 a[4];
            #pragma unroll
            for (int mt = 0; mt < 4; mt++)
                a[mt] = As[(kt * 8 + wm * 4 + mt) * 32 + lane];
            #pragma unroll
            for (int nt = 0; nt < 4; nt++) {
                const int n    = wn * 32 + nt * 8 + (lane >> 2);
                const int rowi = (n >> 6) + dy + 1;
                const int x    = (n & 63) + 1 + dx;
                const int c    = lane & 3;
                const uint32_t b0 = Bs[c * B_CKSTR + rowi * 72 + x];
                const uint32_t b1 = Bs[(c + 4) * B_CKSTR + rowi * 72 + x];
                #pragma unroll
                for (int mt = 0; mt < 4; mt++)
                    mma_f16(acc[mt][nt], (const uint32_t*)&a[mt], b0, b1);
            }
        }
    };

    issueChunk(0);
    for (int i = 0; i < nchunk; i++) {
        asm volatile("cp.async.wait_group 0;" ::: "memory");
        __syncthreads();
        if (i + 1 < nchunk) issueChunk(i + 1);
        compute(i & 1);
    }

    // ---- epilogue
    const int addImg = addDiv ? (img / addDiv) : 0;
    #pragma unroll
    for (int mt = 0; mt < 4; mt++) {
        #pragma unroll
        for (int h = 0; h < 2; h++) {
            const int oc = wm * 64 + mt * 16 + (lane >> 2) + h * 8;
            const float bv = (bias && z == 0) ? bias[oc] : 0.f;
            #pragma unroll
            for (int nt = 0; nt < 4; nt++) {
                const int n = wn * 32 + nt * 8 + 2 * (lane & 3);
                const int r = n >> 6, x = n & 63;
                float v0 = acc[mt][nt][2 * h + 0] + bv;
                float v1 = acc[mt][nt][2 * h + 1] + bv;
                if (addend) {
                    const float2 ad = *(const float2*)(addend
                        + ((long)addImg * HIDC + oc) * HW + (row0 + r) * 64 + x);
                    v0 += ad.x; v1 += ad.y;
                }
                if (doRelu) { v0 = fmaxf(v0, 0.f); v1 = fmaxf(v1, 0.f); }
                if (outMode == 0) {
                    *(float2*)((float*)outp + z * outZStride
                               + ((long)img * HIDC + oc) * HW
                               + (row0 + r) * 64 + x) = make_float2(v0, v1);
                } else if (outMode == 2) {
                    float* op = (float*)outp + z * outZStride
                                + ((long)img * HIDC + oc) * PHW
                                + (row0 + r + 1) * PW + 1 + x;
                    op[0] = v0; op[1] = v1;
                } else {
                    const uint32_t own  = packh2(v0, v1);      // my oc, px x/x+1
                    const uint32_t part = __shfl_xor_sync(0xffffffffu, own, 4);
                    if (((lane >> 2) & 1) == 0) {              // even oc writes pair
                        uint32_t* op = (uint32_t*)outp
                            + ((long)img * (HIDC/2) + (oc >> 1)) * PHW
                            + (row0 + r + 1) * PW + 1 + x;
                        op[0] = (own & 0xFFFFu) | (part << 16);
                        op[1] = (own >> 16) | (part & 0xFFFF0000u);
                    }
                }
            }
        }
    }
}

// ---------------------------------------------------------------------------
// T partial merge: T0 += T1 (float4). Halves the obj-conv epilogue reads.
// ---------------------------------------------------------------------------
__global__ void tmerge_k(float4* __restrict__ t0, const float4* __restrict__ t1) {
    int idx = blockIdx.x * 256 + threadIdx.x;
    if (idx >= BB*HIDC*HW/4) return;
    float4 a = t0[idx];
    const float4 b = t1[idx];
    a.x += b.x; a.y += b.y; a.z += b.z; a.w += b.w;
    t0[idx] = a;
}

// ---------------------------------------------------------------------------
// Fused prep: feats pad+pack | enc pack | gcn pack | ro pack, ONE launch.
// Fragment layout per 16-cin chunk (9216 u32): [kt(9)][mtile(8)][lane(32)][e(4)];
// oc = mtile*16 + (lane>>2) + ((e&1)<<3); cinpair = (lane&3) + ((e>>1)<<2).
// ---------------------------------------------------------------------------
#define NPAD ((long)BB*(CC/2)*PHW)   // 2654208
#define NE (HIDC*CC*9/2)             // 147456
#define NG (HIDC*HIDC*9/2)           // 73728
__global__ void prep_pad_all(const float* __restrict__ f,
                             const float* __restrict__ ew,
                             const float* __restrict__ gw,
                             const float* __restrict__ ro_w,
                             uint32_t* __restrict__ pf,
                             uint32_t* __restrict__ wencp,
                             uint32_t* __restrict__ w2p, uint32_t* __restrict__ wdp,
                             uint32_t* __restrict__ wrof, uint32_t* __restrict__ wroh)
{
    long gi = (long)blockIdx.x * 256 + threadIdx.x;
    if (gi < NPAD) {
        long ch = gi / PHW; int p = (int)(gi % PHW); int y = p / PW, x = p % PW;
        uint32_t v = 0;
        if (y >= 1 && y <= 64 && x >= 1 && x <= 64) {
            int b = (int)(ch >> 7), ck = (int)(ch & 127);
            const float* src = f + ((long)b * CC + 2 * ck) * HW + (y - 1) * 64 + (x - 1);
            v = packh2(src[0], src[HW]);
        }
        pf[gi] = v;
        return;
    }
    int idx = (int)(gi - NPAD);
    if (idx < NE) {
        int chunk = idx / 9216, rem = idx % 9216;
        int kt = rem / 1024, rem2 = rem % 1024;
        int mtile = rem2 / 128, r3 = rem2 % 128;
        int lane = r3 / 4, e = r3 % 4;
        int oc = mtile * 16 + (lane >> 2) + ((e & 1) << 3);
        int cin0 = chunk * 16 + ((lane & 3) + ((e >> 1) << 2)) * 2;
        wencp[idx] = packh2(ew[((long)oc * 257 + cin0) * 9 + kt],
                            ew[((long)oc * 257 + cin0 + 1) * 9 + kt]);
    } else if (idx < NE + NG) {
        int i2 = idx - NE;
        int chunk = i2 / 9216, rem = i2 % 9216;
        int kt = rem / 1024, rem2 = rem % 1024;
        int mtile = rem2 / 128, r3 = rem2 % 128;
        int lane = r3 / 4, e = r3 % 4;
        int oc = mtile * 16 + (lane >> 2) + ((e & 1) << 3);
        int cin0 = chunk * 16 + ((lane & 3) + ((e >> 1) << 2)) * 2;
        float a0 = gw[((long)oc * 2 * HIDC + cin0) * 9 + kt];
        float b0 = gw[((long)oc * 2 * HIDC + HIDC + cin0) * 9 + kt];
        float a1 = gw[((long)oc * 2 * HIDC + cin0 + 1) * 9 + kt];
        float b1 = gw[((long)oc * 2 * HIDC + HIDC + cin0 + 1) * 9 + kt];
        w2p[i2] = packh2(b0, b1);
        wdp[i2] = packh2(a0 - b0, a1 - b1);
    } else if (idx < NE + NG + 1152) {
        int r0 = idx - NE - NG;
        int zz = r0 / 576, r = r0 % 576, tap = r / 64, ck = r % 64;
        int ch0 = zz * 128 + 2 * ck;
        wrof[r0] = packh2(ro_w[ch0 * 9 + tap], ro_w[(ch0 + 1) * 9 + tap]);
    } else if (idx < NE + NG + 1728) {
        int r = idx - NE - NG - 1152, tap = r / 64, ck = r % 64;
        int ch0 = CC + 2 * ck;
        wroh[r] = packh2(ro_w[ch0 * 9 + tap], ro_w[(ch0 + 1) * 9 + tap]);
    }
}

// ---------------------------------------------------------------------------
// Fused enc-per-object + sum-over-objects. grid (16 pxblk, BB, 4 chgrp).
// Loops 8 objects in registers: base read once, states + S written.
// ---------------------------------------------------------------------------
__global__ void __launch_bounds__(256) enc_obj_sum(
    const float* __restrict__ masks, const float* __restrict__ enc_w,
    const float* __restrict__ pbase, uint32_t* __restrict__ pst,
    uint32_t* __restrict__ pS)
{
    __shared__ float wm2[32 * 9];
    const int tid = threadIdx.x;
    const int b = blockIdx.y, cg = blockIdx.z;
    const int p = blockIdx.x * 256 + tid;
    for (int t = tid; t < 288; t += 256) {
        int lch = t / 9, k = t - lch * 9;
        wm2[t] = enc_w[((long)(cg * 32 + lch) * 257 + 256) * 9 + k];
    }
    __syncthreads();
    const int y = p >> 6, x = p & 63;
    const int pp = (y + 1) * PW + x + 1;
    float m[8][9];
    #pragma unroll
    for (int o = 0; o < 8; o++) {
        const float* mk = masks + (long)(b * 8 + o) * HW;
        #pragma unroll
        for (int k = 0; k < 9; k++) {
            int gy = y - 1 + k / 3, gx = x - 1 + k % 3;
            m[o][k] = ((unsigned)gy < 64u && (unsigned)gx < 64u)
                        ? mk[gy * 64 + gx] : 0.f;
        }
    }
    const float* b1p = pbase + (long)b * HIDC * PHW;
    const float* b2p = b1p + (long)BB * HIDC * PHW;
    #pragma unroll 2
    for (int j = 0; j < 16; j++) {
        const int ck = cg * 16 + j;
        const int ch0 = 2 * ck;
        float base0 = b1p[(long)ch0 * PHW + pp] + b2p[(long)ch0 * PHW + pp];
        float base1 = b1p[(long)(ch0+1) * PHW + pp] + b2p[(long)(ch0+1) * PHW + pp];
        float sLo = 0.f, sHi = 0.f;
        #pragma unroll
        for (int o = 0; o < 8; o++) {
            float a0 = base0, a1 = base1;
            #pragma unroll
            for (int k = 0; k < 9; k++) {
                a0 = fmaf(wm2[(2*j) * 9 + k],   m[o][k], a0);
                a1 = fmaf(wm2[(2*j+1) * 9 + k], m[o][k], a1);
            }
            uint32_t h = packh2(fmaxf(a0, 0.f), fmaxf(a1, 0.f));
            pst[((long)(b * 8 + o) * (HIDC/2) + ck) * PHW + pp] = h;
            __half2 hh = *(__half2*)&h;
            sLo += __low2float(hh); sHi += __high2float(hh);
        }
        pS[((long)b * (HIDC/2) + ck) * PHW + pp] = packh2(sLo, sHi);
    }
}
// Vectorized sum-over-objects (uint4) for step 2.
__global__ void sumO4_k(const uint4* __restrict__ st, uint4* __restrict__ S) {
    long idx = (long)blockIdx.x * 256 + threadIdx.x;
    const long N = (long)BB * (HIDC/2) * (PHW/4);
    if (idx >= N) return;
    int b = (int)(idx / ((HIDC/2) * (PHW/4)));
    long r = idx - (long)b * (HIDC/2) * (PHW/4);
    const uint4* pp = st + (long)b * OO * (HIDC/2) * (PHW/4) + r;
    float lo[4] = {0,0,0,0}, hi[4] = {0,0,0,0};
    #pragma unroll
    for (int o = 0; o < OO; o++) {
        uint4 v = pp[(long)o * (HIDC/2) * (PHW/4)];
        const uint32_t* w = (const uint32_t*)&v;
        #pragma unroll
        for (int c = 0; c < 4; c++) {
            __half2 h = *(__half2*)&w[c];
            lo[c] += __low2float(h); hi[c] += __high2float(h);
        }
    }
    uint4 out;
    uint32_t* ow = (uint32_t*)&out;
    #pragma unroll
    for (int c = 0; c < 4; c++) ow[c] = packh2(lo[c], hi[c]);
    S[idx] = out;
}

// ---------------------------------------------------------------------------
// Readout tile kernels: stage 64 ck x 4 padded rows via ONE cp.async round,
// one barrier, then fp32-accum dot over (ck, tap). 2 threads per px split ck.
// ---------------------------------------------------------------------------
__global__ void __launch_bounds__(256) ro_base_k(
    const uint32_t* __restrict__ pfeats, const uint32_t* __restrict__ wrof,
    const float* __restrict__ ro_b, float* __restrict__ rpart)
{
    extern __shared__ __align__(16) uint32_t sm[];
    uint32_t* ws  = sm + RO_TILE_U32;
    float*    red = (float*)(ws + 576);
    const int tid = threadIdx.x;
    const int img = blockIdx.y, z = blockIdx.z, row0 = blockIdx.x * 2;
    const uint32_t* pimg = pfeats + (long)img * (CC/2) * PHW + (long)z * 64 * PHW;
    const uint32_t smb = (uint32_t)__cvta_generic_to_shared(sm);
    #pragma unroll
    for (int j = 0; j < 18; j++) {
        const int o = tid + j * 256;          // 4608 lines
        const int ck = o / 72, rem = o % 72, rI = rem / 18, q = rem % 18;
        CP16(smb + (ck * B_CKSTR + rI * 72 + q * 4) * 4,
             pimg + (long)ck * PHW + (row0 + rI) * PW + q * 4);
    }
    for (int t = tid; t < 576; t += 256) ws[t] = wrof[z * 576 + t];
    asm volatile("cp.async.commit_group;" ::: "memory");
    asm volatile("cp.async.wait_group 0;" ::: "memory");
    __syncthreads();

    const int px = tid & 127, ckh = tid >> 7;
    const int r = px >> 6, x = px & 63;
    float acc = 0.f;
    for (int ck = ckh * 32; ck < ckh * 32 + 32; ck++) {
        #pragma unroll
        for (int tap = 0; tap < 9; tap++) {
            const int dy = tap / 3 - 1, dx = tap % 3 - 1;
            uint32_t bv = sm[ck * B_CKSTR + (r + 1 + dy) * 72 + (x + 1 + dx)];
            float2 bf = __half22float2(*(__half2*)&bv);
            float2 wf = __half22float2(*(__half2*)&ws[tap * 64 + ck]);
            acc = fmaf(bf.x, wf.x, acc);
            acc = fmaf(bf.y, wf.y, acc);
        }
    }
    red[tid] = acc;
    __syncthreads();
    if (tid < 128) {
        float s = red[tid] + red[tid + 128] + (z == 0 ? ro_b[0] : 0.f);
        rpart[((long)z * BB + img) * HW + (row0 + r) * 64 + x] = s;
    }
}
__global__ void __launch_bounds__(256) ro_obj_k(
    const uint32_t* __restrict__ pst, const uint32_t* __restrict__ wroh,
    const float* __restrict__ rpart, float* __restrict__ outp)
{
    extern __shared__ __align__(16) uint32_t sm[];
    uint32_t* ws  = sm + RO_TILE_U32;
    float*    red = (float*)(ws + 576);
    const int tid = threadIdx.x;
    const int img = blockIdx.y, row0 = blockIdx.x * 2;
    const uint32_t* pimg = pst + (long)img * (HIDC/2) * PHW;
    const uint32_t smb = (uint32_t)__cvta_generic_to_shared(sm);
    #pragma unroll
    for (int j = 0; j < 18; j++) {
        const int o = tid + j * 256;
        const int ck = o / 72, rem = o % 72, rI = rem / 18, q = rem % 18;
        CP16(smb + (ck * B_CKSTR + rI * 72 + q * 4) * 4,
             pimg + (long)ck * PHW + (row0 + rI) * PW + q * 4);
    }
    for (int t = tid; t < 576; t += 256) ws[t] = wroh[t];
    asm volatile("cp.async.commit_group;" ::: "memory");
    asm volatile("cp.async.wait_group 0;" ::: "memory");
    __syncthreads();

    const int px = tid & 127, ckh = tid >> 7;
    const int r = px >> 6, x = px & 63;
    float acc = 0.f;
    for (int ck = ckh * 32; ck < ckh * 32 + 32; ck++) {
        #pragma unroll
        for (int tap = 0; tap < 9; tap++) {
            const int dy = tap / 3 - 1, dx = tap % 3 - 1;
            uint32_t bv = sm[ck * B_CKSTR + (r + 1 + dy) * 72 + (x + 1 + dx)];
            float2 bf = __half22float2(*(__half2*)&bv);
            float2 wf = __half22float2(*(__half2*)&ws[tap * 64 + ck]);
            acc = fmaf(bf.x, wf.x, acc);
            acc = fmaf(bf.y, wf.y, acc);
        }
    }
    red[tid] = acc;
    __syncthreads();
    if (tid < 128) {
        const int b = img >> 3;
        const long po = (long)b * HW + (row0 + r) * 64 + x;
        float zl = red[tid] + red[tid + 128]
                 + rpart[po] + rpart[(long)BB * HW + po];
        outp[(long)img * HW + (row0 + r) * 64 + x] = 1.f / (1.f + expf(-zl));
    }
}

// ---------------------------------------------------------------------------
extern "C" void kernel_launch(void* const* d_in, const int* in_sizes, int n_in,
                              void* d_out, int out_size)
{
    const float* feats = (const float*)d_in[0];
    const float* masks = (const float*)d_in[1];
    const float* enc_w = (const float*)d_in[4];
    const float* enc_b = (const float*)d_in[5];
    const float* gcn_w = (const float*)d_in[6];
    const float* gcn_b = (const float*)d_in[7];
    const float* ro_w  = (const float*)d_in[8];
    const float* ro_b  = (const float*)d_in[9];
    float* outp = (float*)d_out;

    uint32_t *pst0, *pst1, *pS, *pfeats, *wencp, *w2p, *wdp, *wrof, *wroh;
    float *pbase, *T, *rpart;
    cudaGetSymbolAddress((void**)&pst0,   g_pst0);
    cudaGetSymbolAddress((void**)&pst1,   g_pst1);
    cudaGetSymbolAddress((void**)&pS,     g_pS);
    cudaGetSymbolAddress((void**)&pfeats, g_pfeats);
    cudaGetSymbolAddress((void**)&pbase,  g_pbase);
    cudaGetSymbolAddress((void**)&T,      g_T);
    cudaGetSymbolAddress((void**)&rpart,  g_rpart);
    cudaGetSymbolAddress((void**)&wencp,  g_wencp);
    cudaGetSymbolAddress((void**)&w2p,    g_w2p);
    cudaGetSymbolAddress((void**)&wdp,    g_wdp);
    cudaGetSymbolAddress((void**)&wrof,   g_wrof);
    cudaGetSymbolAddress((void**)&wroh,   g_wroh);

    cudaFuncSetAttribute(conv_mma<64>,
                         cudaFuncAttributeMaxDynamicSharedMemorySize, CONV_DSM);
    cudaFuncSetAttribute(conv_mma<128>,
                         cudaFuncAttributeMaxDynamicSharedMemorySize, CONV_DSM);
    cudaFuncSetAttribute(ro_base_k,
                         cudaFuncAttributeMaxDynamicSharedMemorySize, RO_DSM);
    cudaFuncSetAttribute(ro_obj_k,
                         cudaFuncAttributeMaxDynamicSharedMemorySize, RO_DSM);

    // fused pad + weight prep
    {
        long total = NPAD + NE + NG + 1728;
        prep_pad_all<<<(int)((total + 255) / 256), 256>>>(
            feats, enc_w, gcn_w, ro_w, pfeats, wencp, w2p, wdp, wrof, wroh);
    }

    // enc base, K-split z=2: partials -> pbase[0], pbase[zstride]
    conv_mma<128><<<dim3(32, BB, 2), 256, CONV_DSM>>>(
        pfeats, (long)(CC/2)*PHW, wencp, enc_b, nullptr, 0,
        pbase, (long)BB*HIDC*PHW, 2, 0);
    // fused enc per-object + sumO -> pst0, pS
    enc_obj_sum<<<dim3(16, BB, 4), 256>>>(masks, enc_w, pbase, pst0, pS);

    const int tmN = BB*HIDC*HW/4;
    // step 1
    conv_mma<64><<<dim3(32, BB, 2), 256, CONV_DSM>>>(
        pS, (long)(HIDC/2)*PHW, w2p, gcn_b, nullptr, 0,
        T, (long)BB*HIDC*HW, 0, 0);
    tmerge_k<<<(tmN + 255)/256, 256>>>((float4*)T, (const float4*)(T + (long)BB*HIDC*HW));
    conv_mma<128><<<dim3(32, BB*OO, 1), 256, CONV_DSM>>>(
        pst0, (long)(HIDC/2)*PHW, wdp, nullptr,
        T, OO, pst1, 0, 1, 1);
    sumO4_k<<<(int)(((long)BB*(HIDC/2)*(PHW/4) + 255)/256), 256>>>(
        (const uint4*)pst1, (uint4*)pS);

    // step 2
    conv_mma<64><<<dim3(32, BB, 2), 256, CONV_DSM>>>(
        pS, (long)(HIDC/2)*PHW, w2p, gcn_b, nullptr, 0,
        T, (long)BB*HIDC*HW, 0, 0);
    tmerge_k<<<(tmN + 255)/256, 256>>>((float4*)T, (const float4*)(T + (long)BB*HIDC*HW));
    conv_mma<128><<<dim3(32, BB*OO, 1), 256, CONV_DSM>>>(
        pst1, (long)(HIDC/2)*PHW, wdp, nullptr,
        T, OO, pst0, 0, 1, 1);

    ro_base_k<<<dim3(32, BB, 2), 256, RO_DSM>>>(pfeats, wrof, ro_b, rpart);
    ro_obj_k<<<dim3(32, BB*OO), 256, RO_DSM>>>(pst0, wroh, rpart, outp);
}

// round 17
// speedup vs baseline: 1.1896x; 1.0114x over previous
#include <cuda_runtime.h>
#include <cuda_fp16.h>
#include <cstdint>
#include <math.h>

#define HW 4096
#define PW 72
#define PHW 5184          // 72*72 ; half2 rows 16B-aligned
#define HIDC 128
#define BB 4
#define OO 8
#define CC 256

// One chunk = 16 cin x 9 taps. A: 9kt*8mtile*32lane*16B = 36864 B.
// B: 8 ckpairs x (4 rows x 72 u32), ck stride 296 u32 (bank-spread) = 9472 B.
#define A_STAGE 36864
#define B_CKSTR 296
#define B_STAGE 9472
#define STAGE (A_STAGE + B_STAGE)      // 46336
#define CONV_DSM (2*STAGE)             // 92672 -> 2 CTA/SM

// Readout tile kernels: 64 ck x 4 rows staged once. 64*296 u32 tile.
#define RO_TILE_U32 18944
#define RO_DSM ((RO_TILE_U32 + 576)*4 + 1024)   // tile + ws + reduce buf

// ---------------------------------------------------------------------------
// Scratch (device globals; allocation forbidden). Zero-initialized at load;
// borders of padded buffers are NEVER written -> stay zero across replays.
// Padded activation buffers are half2, cin-pair interleaved: [ch/2][y][x].
// ---------------------------------------------------------------------------
__device__ uint32_t g_pst0[BB*OO*(HIDC/2)*PHW];  // states ping (half2)
__device__ uint32_t g_pst1[BB*OO*(HIDC/2)*PHW];  // states pong (half2)
__device__ uint32_t g_pS[BB*(HIDC/2)*PHW];       // sum-over-objects (half2)
__device__ uint32_t g_pfeats[BB*(CC/2)*PHW];     // feats (half2)
__device__ float    g_pbase[2*BB*HIDC*PHW];      // enc base partials (fp32 padded)
__device__ float    g_T[2*BB*HIDC*HW];           // gcn term partials (fp32)
__device__ float    g_rpart[2*BB*HW];            // readout base partials
__device__ uint32_t g_wencp[HIDC*CC*9/2];        // packed fp16 enc weights
__device__ uint32_t g_w2p[HIDC*HIDC*9/2];        // packed W2
__device__ uint32_t g_wdp[HIDC*HIDC*9/2];        // packed W1-W2
__device__ uint32_t g_wrof[2*9*64];              // packed ro feats weights
__device__ uint32_t g_wroh[9*64];                // packed ro hid weights

// ---------------------------------------------------------------------------
#define CP16(dst, src) \
    asm volatile("cp.async.cg.shared.global [%0], [%1], 16;" \
                 :: "r"(dst), "l"(src) : "memory")

__device__ __forceinline__ uint32_t packh2(float lo, float hi) {
    __half2 h = __floats2half2_rn(lo, hi);
    return *(uint32_t*)&h;
}
__device__ __forceinline__ void mma_f16(float* c, const uint32_t* a,
                                        uint32_t b0, uint32_t b1) {
    asm("mma.sync.aligned.m16n8k16.row.col.f32.f16.f16.f32 "
        "{%0,%1,%2,%3}, {%4,%5,%6,%7}, {%8,%9}, {%0,%1,%2,%3};"
        : "+f"(c[0]), "+f"(c[1]), "+f"(c[2]), "+f"(c[3])
        : "r"(a[0]), "r"(a[1]), "r"(a[2]), "r"(a[3]), "r"(b0), "r"(b1));
}

// ---------------------------------------------------------------------------
// fp16 implicit-GEMM 3x3 conv (R12-proven core, UNCHANGED). M=128 oc,
// N=128 px (2 rows), chunk = 16 cin x 9 taps. 2-stage cp.async, ONE barrier
// per chunk: at iter i the barrier proves compute(i-1) done, so issue(i+1)
// may overwrite stage (i+1)&1 (computed at i-1); wait_group(0) proves chunk
// i landed. K-split via blockIdx.z (bias only on z==0).
// outMode: 0 = fp32 unpadded, 1 = half2 padded (oc-pair via shfl), 2 = fp32 padded.
// ---------------------------------------------------------------------------
template<int CIN>
__global__ void __launch_bounds__(256, 2)
conv_mma(const uint32_t* __restrict__ pin, long imgCkStride,
         const uint32_t* __restrict__ wpack,
         const float* __restrict__ bias,
         const float* __restrict__ addend, int addDiv,
         void* __restrict__ outp, long outZStride, int outMode, int doRelu)
{
    extern __shared__ __align__(16) char dsm[];
    const int tid  = threadIdx.x;
    const int lane = tid & 31, wid = tid >> 5;
    const int wm   = wid & 1,  wn  = wid >> 1;
    const int img  = blockIdx.y, row0 = blockIdx.x * 2, z = blockIdx.z;
    constexpr int nchunk = CIN / 16;
    const uint32_t* pimg = pin + (long)img * imgCkStride + (long)z * (CIN/2) * PHW;
    const uint32_t* wp   = wpack + (long)z * (CIN/16) * 9216;
    const uint32_t smbase = (uint32_t)__cvta_generic_to_shared(dsm);

    float acc[4][4][4];
    #pragma unroll
    for (int mt = 0; mt < 4; mt++)
        #pragma unroll
        for (int nt = 0; nt < 4; nt++)
            #pragma unroll
            for (int e = 0; e < 4; e++) acc[mt][nt][e] = 0.f;

    auto issueChunk = [&](int ci) {
        const uint32_t abase = smbase + (ci & 1) * STAGE;
        const uint32_t bbase = abase + A_STAGE;
        const uint32_t* asrc = wp + (long)ci * 9216;
        #pragma unroll
        for (int j = 0; j < 9; j++) {                 // 2304 16B lines
            const int u = tid + j * 256;
            CP16(abase + u * 16, asrc + u * 4);
        }
        #pragma unroll
        for (int v = 0; v < 3; v++) {                 // 576 16B lines
            const int o = tid + v * 256;
            if (o < 576) {
                const int ck = o / 72, rem = o % 72;
                const int rI = rem / 18, q = rem % 18;
                const uint32_t* src = pimg + (long)(ci * 8 + ck) * PHW
                                      + (row0 + rI) * PW + q * 4;
                CP16(bbase + (ck * B_CKSTR + rI * 72 + q * 4) * 4, src);
            }
        }
        asm volatile("cp.async.commit_group;" ::: "memory");
    };

    auto compute = [&](int s) {
        const uint4*    As = (const uint4*)(dsm + s * STAGE);
        const uint32_t* Bs = (const uint32_t*)(dsm + s * STAGE + A_STAGE);
        #pragma unroll
        for (int kt = 0; kt < 9; kt++) {
            const int dy = kt / 3 - 1, dx = kt % 3 - 1;
            uint4 a[4];
            #pragma unroll
            for (int mt = 0; mt < 4; mt++)
                a[mt] = As[(kt * 8 + wm * 4 + mt) * 32 + lane];
            #pragma unroll
            for (int nt = 0; nt < 4; nt++) {
                const int n    = wn * 32 + nt * 8 + (lane >> 2);
                const int rowi = (n >> 6) + dy + 1;
                const int x    = (n & 63) + 1 + dx;
                const int c    = lane & 3;
                const uint32_t b0 = Bs[c * B_CKSTR + rowi * 72 + x];
                const uint32_t b1 = Bs[(c + 4) * B_CKSTR + rowi * 72 + x];
                #pragma unroll
                for (int mt = 0; mt < 4; mt++)
                    mma_f16(acc[mt][nt], (const uint32_t*)&a[mt], b0, b1);
            }
        }
    };

    issueChunk(0);
    for (int i = 0; i < nchunk; i++) {
        asm volatile("cp.async.wait_group 0;" ::: "memory");
        __syncthreads();
        if (i + 1 < nchunk) issueChunk(i + 1);
        compute(i & 1);
    }

    // ---- epilogue
    const int addImg = addDiv ? (img / addDiv) : 0;
    #pragma unroll
    for (int mt = 0; mt < 4; mt++) {
        #pragma unroll
        for (int h = 0; h < 2; h++) {
            const int oc = wm * 64 + mt * 16 + (lane >> 2) + h * 8;
            const float bv = (bias && z == 0) ? bias[oc] : 0.f;
            #pragma unroll
            for (int nt = 0; nt < 4; nt++) {
                const int n = wn * 32 + nt * 8 + 2 * (lane & 3);
                const int r = n >> 6, x = n & 63;
                float v0 = acc[mt][nt][2 * h + 0] + bv;
                float v1 = acc[mt][nt][2 * h + 1] + bv;
                if (addend) {
                    const float2 ad = *(const float2*)(addend
                        + ((long)addImg * HIDC + oc) * HW + (row0 + r) * 64 + x);
                    v0 += ad.x; v1 += ad.y;
                }
                if (doRelu) { v0 = fmaxf(v0, 0.f); v1 = fmaxf(v1, 0.f); }
                if (outMode == 0) {
                    *(float2*)((float*)outp + z * outZStride
                               + ((long)img * HIDC + oc) * HW
                               + (row0 + r) * 64 + x) = make_float2(v0, v1);
                } else if (outMode == 2) {
                    float* op = (float*)outp + z * outZStride
                                + ((long)img * HIDC + oc) * PHW
                                + (row0 + r + 1) * PW + 1 + x;
                    op[0] = v0; op[1] = v1;
                } else {
                    const uint32_t own  = packh2(v0, v1);      // my oc, px x/x+1
                    const uint32_t part = __shfl_xor_sync(0xffffffffu, own, 4);
                    if (((lane >> 2) & 1) == 0) {              // even oc writes pair
                        uint32_t* op = (uint32_t*)outp
                            + ((long)img * (HIDC/2) + (oc >> 1)) * PHW
                            + (row0 + r + 1) * PW + 1 + x;
                        op[0] = (own & 0xFFFFu) | (part << 16);
                        op[1] = (own >> 16) | (part & 0xFFFF0000u);
                    }
                }
            }
        }
    }
}

// ---------------------------------------------------------------------------
// T partial merge: T0 += T1 (float4). Halves the obj-conv epilogue reads.
// ---------------------------------------------------------------------------
__global__ void tmerge_k(float4* __restrict__ t0, const float4* __restrict__ t1) {
    int idx = blockIdx.x * 256 + threadIdx.x;
    if (idx >= BB*HIDC*HW/4) return;
    float4 a = t0[idx];
    const float4 b = t1[idx];
    a.x += b.x; a.y += b.y; a.z += b.z; a.w += b.w;
    t0[idx] = a;
}

// ---------------------------------------------------------------------------
// Fused prep: feats pad+pack (uint2-vectorized) | enc pack | gcn pack |
// ro pack, ONE launch. Fragment layout per 16-cin chunk (9216 u32):
// [kt(9)][mtile(8)][lane(32)][e(4)];
// oc = mtile*16 + (lane>>2) + ((e&1)<<3); cinpair = (lane&3) + ((e>>1)<<2).
// ---------------------------------------------------------------------------
#define NPAD  ((long)BB*(CC/2)*PHW)   // 2654208 (even; PW even -> pairs in-row)
#define NPADV (NPAD/2)                // 1327104 uint2 elements
#define NE (HIDC*CC*9/2)              // 147456
#define NG (HIDC*HIDC*9/2)            // 73728
__global__ void prep_pad_all(const float* __restrict__ f,
                             const float* __restrict__ ew,
                             const float* __restrict__ gw,
                             const float* __restrict__ ro_w,
                             uint32_t* __restrict__ pf,
                             uint32_t* __restrict__ wencp,
                             uint32_t* __restrict__ w2p, uint32_t* __restrict__ wdp,
                             uint32_t* __restrict__ wrof, uint32_t* __restrict__ wroh)
{
    long gi = (long)blockIdx.x * 256 + threadIdx.x;
    if (gi < NPADV) {
        const long u = gi * 2;
        long ch = u / PHW; int p = (int)(u % PHW);
        const int y = p / PW, x = p % PW;     // x even -> x+1 in same row
        uint32_t v0 = 0, v1 = 0;
        const int b = (int)(ch >> 7), ck = (int)(ch & 127);
        const float* src = f + ((long)b * CC + 2 * ck) * HW + (y - 1) * 64 + (x - 1);
        if (y >= 1 && y <= 64) {
            if (x >= 1 && x <= 64)     v0 = packh2(src[0], src[HW]);
            if (x + 1 >= 1 && x + 1 <= 64) v1 = packh2(src[1], src[HW + 1]);
        }
        ((uint2*)pf)[gi] = make_uint2(v0, v1);
        return;
    }
    int idx = (int)(gi - NPADV);
    if (idx < NE) {
        int chunk = idx / 9216, rem = idx % 9216;
        int kt = rem / 1024, rem2 = rem % 1024;
        int mtile = rem2 / 128, r3 = rem2 % 128;
        int lane = r3 / 4, e = r3 % 4;
        int oc = mtile * 16 + (lane >> 2) + ((e & 1) << 3);
        int cin0 = chunk * 16 + ((lane & 3) + ((e >> 1) << 2)) * 2;
        wencp[idx] = packh2(ew[((long)oc * 257 + cin0) * 9 + kt],
                            ew[((long)oc * 257 + cin0 + 1) * 9 + kt]);
    } else if (idx < NE + NG) {
        int i2 = idx - NE;
        int chunk = i2 / 9216, rem = i2 % 9216;
        int kt = rem / 1024, rem2 = rem % 1024;
        int mtile = rem2 / 128, r3 = rem2 % 128;
        int lane = r3 / 4, e = r3 % 4;
        int oc = mtile * 16 + (lane >> 2) + ((e & 1) << 3);
        int cin0 = chunk * 16 + ((lane & 3) + ((e >> 1) << 2)) * 2;
        float a0 = gw[((long)oc * 2 * HIDC + cin0) * 9 + kt];
        float b0 = gw[((long)oc * 2 * HIDC + HIDC + cin0) * 9 + kt];
        float a1 = gw[((long)oc * 2 * HIDC + cin0 + 1) * 9 + kt];
        float b1 = gw[((long)oc * 2 * HIDC + HIDC + cin0 + 1) * 9 + kt];
        w2p[i2] = packh2(b0, b1);
        wdp[i2] = packh2(a0 - b0, a1 - b1);
    } else if (idx < NE + NG + 1152) {
        int r0 = idx - NE - NG;
        int zz = r0 / 576, r = r0 % 576, tap = r / 64, ck = r % 64;
        int ch0 = zz * 128 + 2 * ck;
        wrof[r0] = packh2(ro_w[ch0 * 9 + tap], ro_w[(ch0 + 1) * 9 + tap]);
    } else if (idx < NE + NG + 1728) {
        int r = idx - NE - NG - 1152, tap = r / 64, ck = r % 64;
        int ch0 = CC + 2 * ck;
        wroh[r] = packh2(ro_w[ch0 * 9 + tap], ro_w[(ch0 + 1) * 9 + tap]);
    }
}

// ---------------------------------------------------------------------------
// Fused enc-per-object + sum-over-objects. grid (16 pxblk, BB, 8 chgrp).
// Loops 8 objects in registers: base read once, states + S written.
// Same per-output arithmetic order as before -> bit-identical results.
// ---------------------------------------------------------------------------
__global__ void __launch_bounds__(256) enc_obj_sum(
    const float* __restrict__ masks, const float* __restrict__ enc_w,
    const float* __restrict__ pbase, uint32_t* __restrict__ pst,
    uint32_t* __restrict__ pS)
{
    __shared__ float wm2[16 * 9];
    const int tid = threadIdx.x;
    const int b = blockIdx.y, cg = blockIdx.z;   // cg: 0..7 (8 ck each)
    const int p = blockIdx.x * 256 + tid;
    for (int t = tid; t < 144; t += 256) {
        int lch = t / 9, k = t - lch * 9;
        wm2[t] = enc_w[((long)(cg * 16 + lch) * 257 + 256) * 9 + k];
    }
    __syncthreads();
    const int y = p >> 6, x = p & 63;
    const int pp = (y + 1) * PW + x + 1;
    float m[8][9];
    #pragma unroll
    for (int o = 0; o < 8; o++) {
        const float* mk = masks + (long)(b * 8 + o) * HW;
        #pragma unroll
        for (int k = 0; k < 9; k++) {
            int gy = y - 1 + k / 3, gx = x - 1 + k % 3;
            m[o][k] = ((unsigned)gy < 64u && (unsigned)gx < 64u)
                        ? mk[gy * 64 + gx] : 0.f;
        }
    }
    const float* b1p = pbase + (long)b * HIDC * PHW;
    const float* b2p = b1p + (long)BB * HIDC * PHW;
    #pragma unroll 2
    for (int j = 0; j < 8; j++) {
        const int ck = cg * 8 + j;
        const int ch0 = 2 * ck;
        float base0 = b1p[(long)ch0 * PHW + pp] + b2p[(long)ch0 * PHW + pp];
        float base1 = b1p[(long)(ch0+1) * PHW + pp] + b2p[(long)(ch0+1) * PHW + pp];
        float sLo = 0.f, sHi = 0.f;
        #pragma unroll
        for (int o = 0; o < 8; o++) {
            float a0 = base0, a1 = base1;
            #pragma unroll
            for (int k = 0; k < 9; k++) {
                a0 = fmaf(wm2[(2*j) * 9 + k],   m[o][k], a0);
                a1 = fmaf(wm2[(2*j+1) * 9 + k], m[o][k], a1);
            }
            uint32_t h = packh2(fmaxf(a0, 0.f), fmaxf(a1, 0.f));
            pst[((long)(b * 8 + o) * (HIDC/2) + ck) * PHW + pp] = h;
            __half2 hh = *(__half2*)&h;
            sLo += __low2float(hh); sHi += __high2float(hh);
        }
        pS[((long)b * (HIDC/2) + ck) * PHW + pp] = packh2(sLo, sHi);
    }
}
// Vectorized sum-over-objects (uint4) for step 2.
__global__ void sumO4_k(const uint4* __restrict__ st, uint4* __restrict__ S) {
    long idx = (long)blockIdx.x * 256 + threadIdx.x;
    const long N = (long)BB * (HIDC/2) * (PHW/4);
    if (idx >= N) return;
    int b = (int)(idx / ((HIDC/2) * (PHW/4)));
    long r = idx - (long)b * (HIDC/2) * (PHW/4);
    const uint4* pp = st + (long)b * OO * (HIDC/2) * (PHW/4) + r;
    float lo[4] = {0,0,0,0}, hi[4] = {0,0,0,0};
    #pragma unroll
    for (int o = 0; o < OO; o++) {
        uint4 v = pp[(long)o * (HIDC/2) * (PHW/4)];
        const uint32_t* w = (const uint32_t*)&v;
        #pragma unroll
        for (int c = 0; c < 4; c++) {
            __half2 h = *(__half2*)&w[c];
            lo[c] += __low2float(h); hi[c] += __high2float(h);
        }
    }
    uint4 out;
    uint32_t* ow = (uint32_t*)&out;
    #pragma unroll
    for (int c = 0; c < 4; c++) ow[c] = packh2(lo[c], hi[c]);
    S[idx] = out;
}

// ---------------------------------------------------------------------------
// Readout tile kernels: stage 64 ck x 4 padded rows via ONE cp.async round,
// one barrier, then fp32-accum dot over (ck, tap). 2 threads per px split ck.
// ---------------------------------------------------------------------------
__global__ void __launch_bounds__(256) ro_base_k(
    const uint32_t* __restrict__ pfeats, const uint32_t* __restrict__ wrof,
    const float* __restrict__ ro_b, float* __restrict__ rpart)
{
    extern __shared__ __align__(16) uint32_t sm[];
    uint32_t* ws  = sm + RO_TILE_U32;
    float*    red = (float*)(ws + 576);
    const int tid = threadIdx.x;
    const int img = blockIdx.y, z = blockIdx.z, row0 = blockIdx.x * 2;
    const uint32_t* pimg = pfeats + (long)img * (CC/2) * PHW + (long)z * 64 * PHW;
    const uint32_t smb = (uint32_t)__cvta_generic_to_shared(sm);
    #pragma unroll
    for (int j = 0; j < 18; j++) {
        const int o = tid + j * 256;          // 4608 lines
        const int ck = o / 72, rem = o % 72, rI = rem / 18, q = rem % 18;
        CP16(smb + (ck * B_CKSTR + rI * 72 + q * 4) * 4,
             pimg + (long)ck * PHW + (row0 + rI) * PW + q * 4);
    }
    for (int t = tid; t < 576; t += 256) ws[t] = wrof[z * 576 + t];
    asm volatile("cp.async.commit_group;" ::: "memory");
    asm volatile("cp.async.wait_group 0;" ::: "memory");
    __syncthreads();

    const int px = tid & 127, ckh = tid >> 7;
    const int r = px >> 6, x = px & 63;
    float acc = 0.f;
    for (int ck = ckh * 32; ck < ckh * 32 + 32; ck++) {
        #pragma unroll
        for (int tap = 0; tap < 9; tap++) {
            const int dy = tap / 3 - 1, dx = tap % 3 - 1;
            uint32_t bv = sm[ck * B_CKSTR + (r + 1 + dy) * 72 + (x + 1 + dx)];
            float2 bf = __half22float2(*(__half2*)&bv);
            float2 wf = __half22float2(*(__half2*)&ws[tap * 64 + ck]);
            acc = fmaf(bf.x, wf.x, acc);
            acc = fmaf(bf.y, wf.y, acc);
        }
    }
    red[tid] = acc;
    __syncthreads();
    if (tid < 128) {
        float s = red[tid] + red[tid + 128] + (z == 0 ? ro_b[0] : 0.f);
        rpart[((long)z * BB + img) * HW + (row0 + r) * 64 + x] = s;
    }
}
__global__ void __launch_bounds__(256) ro_obj_k(
    const uint32_t* __restrict__ pst, const uint32_t* __restrict__ wroh,
    const float* __restrict__ rpart, float* __restrict__ outp)
{
    extern __shared__ __align__(16) uint32_t sm[];
    uint32_t* ws  = sm + RO_TILE_U32;
    float*    red = (float*)(ws + 576);
    const int tid = threadIdx.x;
    const int img = blockIdx.y, row0 = blockIdx.x * 2;
    const uint32_t* pimg = pst + (long)img * (HIDC/2) * PHW;
    const uint32_t smb = (uint32_t)__cvta_generic_to_shared(sm);
    #pragma unroll
    for (int j = 0; j < 18; j++) {
        const int o = tid + j * 256;
        const int ck = o / 72, rem = o % 72, rI = rem / 18, q = rem % 18;
        CP16(smb + (ck * B_CKSTR + rI * 72 + q * 4) * 4,
             pimg + (long)ck * PHW + (row0 + rI) * PW + q * 4);
    }
    for (int t = tid; t < 576; t += 256) ws[t] = wroh[t];
    asm volatile("cp.async.commit_group;" ::: "memory");
    asm volatile("cp.async.wait_group 0;" ::: "memory");
    __syncthreads();

    const int px = tid & 127, ckh = tid >> 7;
    const int r = px >> 6, x = px & 63;
    float acc = 0.f;
    for (int ck = ckh * 32; ck < ckh * 32 + 32; ck++) {
        #pragma unroll
        for (int tap = 0; tap < 9; tap++) {
            const int dy = tap / 3 - 1, dx = tap % 3 - 1;
            uint32_t bv = sm[ck * B_CKSTR + (r + 1 + dy) * 72 + (x + 1 + dx)];
            float2 bf = __half22float2(*(__half2*)&bv);
            float2 wf = __half22float2(*(__half2*)&ws[tap * 64 + ck]);
            acc = fmaf(bf.x, wf.x, acc);
            acc = fmaf(bf.y, wf.y, acc);
        }
    }
    red[tid] = acc;
    __syncthreads();
    if (tid < 128) {
        const int b = img >> 3;
        const long po = (long)b * HW + (row0 + r) * 64 + x;
        float zl = red[tid] + red[tid + 128]
                 + rpart[po] + rpart[(long)BB * HW + po];
        outp[(long)img * HW + (row0 + r) * 64 + x] = 1.f / (1.f + expf(-zl));
    }
}

// ---------------------------------------------------------------------------
extern "C" void kernel_launch(void* const* d_in, const int* in_sizes, int n_in,
                              void* d_out, int out_size)
{
    const float* feats = (const float*)d_in[0];
    const float* masks = (const float*)d_in[1];
    const float* enc_w = (const float*)d_in[4];
    const float* enc_b = (const float*)d_in[5];
    const float* gcn_w = (const float*)d_in[6];
    const float* gcn_b = (const float*)d_in[7];
    const float* ro_w  = (const float*)d_in[8];
    const float* ro_b  = (const float*)d_in[9];
    float* outp = (float*)d_out;

    uint32_t *pst0, *pst1, *pS, *pfeats, *wencp, *w2p, *wdp, *wrof, *wroh;
    float *pbase, *T, *rpart;
    cudaGetSymbolAddress((void**)&pst0,   g_pst0);
    cudaGetSymbolAddress((void**)&pst1,   g_pst1);
    cudaGetSymbolAddress((void**)&pS,     g_pS);
    cudaGetSymbolAddress((void**)&pfeats, g_pfeats);
    cudaGetSymbolAddress((void**)&pbase,  g_pbase);
    cudaGetSymbolAddress((void**)&T,      g_T);
    cudaGetSymbolAddress((void**)&rpart,  g_rpart);
    cudaGetSymbolAddress((void**)&wencp,  g_wencp);
    cudaGetSymbolAddress((void**)&w2p,    g_w2p);
    cudaGetSymbolAddress((void**)&wdp,    g_wdp);
    cudaGetSymbolAddress((void**)&wrof,   g_wrof);
    cudaGetSymbolAddress((void**)&wroh,   g_wroh);

    cudaFuncSetAttribute(conv_mma<64>,
                         cudaFuncAttributeMaxDynamicSharedMemorySize, CONV_DSM);
    cudaFuncSetAttribute(conv_mma<128>,
                         cudaFuncAttributeMaxDynamicSharedMemorySize, CONV_DSM);
    cudaFuncSetAttribute(ro_base_k,
                         cudaFuncAttributeMaxDynamicSharedMemorySize, RO_DSM);
    cudaFuncSetAttribute(ro_obj_k,
                         cudaFuncAttributeMaxDynamicSharedMemorySize, RO_DSM);

    // fused pad (uint2) + weight prep
    {
        long total = NPADV + NE + NG + 1728;
        prep_pad_all<<<(int)((total + 255) / 256), 256>>>(
            feats, enc_w, gcn_w, ro_w, pfeats, wencp, w2p, wdp, wrof, wroh);
    }

    // enc base, K-split z=2: partials -> pbase[0], pbase[zstride]
    conv_mma<128><<<dim3(32, BB, 2), 256, CONV_DSM>>>(
        pfeats, (long)(CC/2)*PHW, wencp, enc_b, nullptr, 0,
        pbase, (long)BB*HIDC*PHW, 2, 0);
    // fused enc per-object + sumO -> pst0, pS  (8 chgroups)
    enc_obj_sum<<<dim3(16, BB, 8), 256>>>(masks, enc_w, pbase, pst0, pS);

    const int tmN = BB*HIDC*HW/4;
    // step 1
    conv_mma<64><<<dim3(32, BB, 2), 256, CONV_DSM>>>(
        pS, (long)(HIDC/2)*PHW, w2p, gcn_b, nullptr, 0,
        T, (long)BB*HIDC*HW, 0, 0);
    tmerge_k<<<(tmN + 255)/256, 256>>>((float4*)T, (const float4*)(T + (long)BB*HIDC*HW));
    conv_mma<128><<<dim3(32, BB*OO, 1), 256, CONV_DSM>>>(
        pst0, (long)(HIDC/2)*PHW, wdp, nullptr,
        T, OO, pst1, 0, 1, 1);
    sumO4_k<<<(int)(((long)BB*(HIDC/2)*(PHW/4) + 255)/256), 256>>>(
        (const uint4*)pst1, (uint4*)pS);

    // step 2
    conv_mma<64><<<dim3(32, BB, 2), 256, CONV_DSM>>>(
        pS, (long)(HIDC/2)*PHW, w2p, gcn_b, nullptr, 0,
        T, (long)BB*HIDC*HW, 0, 0);
    tmerge_k<<<(tmN + 255)/256, 256>>>((float4*)T, (const float4*)(T + (long)BB*HIDC*HW));
    conv_mma<128><<<dim3(32, BB*OO, 1), 256, CONV_DSM>>>(
        pst1, (long)(HIDC/2)*PHW, wdp, nullptr,
        T, OO, pst0, 0, 1, 1);

    ro_base_k<<<dim3(32, BB, 2), 256, RO_DSM>>>(pfeats, wrof, ro_b, rpart);
    ro_obj_k<<<dim3(32, BB*OO), 256, RO_DSM>>>(pst0, wroh, rpart, outp);
}